// round 15
// baseline (speedup 1.0000x reference)
#include <cuda_runtime.h>
#include <cuda_bf16.h>
#include <cstdint>
#include <math.h>

// Problem constants
constexpr int BB = 1024;
constexpr int TT = 120;
constexpr int EE = 50;
constexpr int HH = 300;
constexpr int CC = 5;
constexpr int KTOT = EE + HH;        // 350
constexpr int KP = 352;              // K padded (22 * 16), cols 350/351 zero
constexpr int NZ = 4 * HH;           // 1200
constexpr int NZP = 1224;            // 17 * 72 permuted cols

// Tiling: grid (8, 17) = 136 blocks (one wave, 1 block/SM), 256 threads.
constexpr int GM = 128;
constexpr int GN = 72;               // 18 positions * 4 gates
constexpr int POSB = 18;
constexpr int NT = GN / 8;           // 9 n-tiles
constexpr int NGRP = 17;             // blocks per row-group (same rb)

// smem: A[128][720B] + W[72][720B] (720B row stride, conflict-free)
constexpr int AS_STRIDE = 720;
constexpr int AS_BYTES = GM * AS_STRIDE;       // 92160
constexpr int WS_BYTES = GN * AS_STRIDE;       // 51840
constexpr int DYN_BYTES = AS_BYTES + WS_BYTES; // 144000
constexpr int WCH = GN * 44;         // W 16B chunks

// CE kernel
constexpr int TOKENS = BB * TT;
constexpr int CE_TB = 128;
constexpr int CE_BLOCKS = TOKENS / CE_TB;      // 960

// ----------------- device scratch (no cudaMalloc allowed) -----------------
__device__ __align__(16) __nv_bfloat16 g_A[(TT + 1) * BB * KP]; // 87.2 MB
__device__ __align__(16) __nv_bfloat16 g_W[NZP * KP];           // 0.86 MB
__device__ float    g_biasP[NZP];
__device__ double   g_bsum[CE_BLOCKS];
__device__ int      g_bcnt[CE_BLOCKS];
__device__ int      g_mask_is_byte;

// Per-row-group barriers, 256B padded (avoid L2 hash bit-7 pair-collide).
struct __align__(256) GroupBar { unsigned cnt; unsigned phase; unsigned pad[62]; };
__device__ GroupBar g_bars[8];       // cnt returns to 0; phase monotonic

// ----------------- scalar helpers -----------------
__device__ __forceinline__ float rcp_fast(float x) {
    float y;
    asm("rcp.approx.f32 %0, %1;" : "=f"(y) : "f"(x));
    return y;
}

// exp(x) with zero MUFU: FMA-only range reduction + 2^f poly + exponent add.
__device__ __forceinline__ float exp_fma(float x) {
    float x2 = x * 1.4426950408889634f;
    x2 = fminf(fmaxf(x2, -30.0f), 30.0f);
    float biased = x2 + 12582912.0f;            // 1.5 * 2^23
    int   ni = __float_as_int(biased) - 0x4B400000;
    float n = biased - 12582912.0f;
    float f = x2 - n;
    float p = 1.5403530e-4f;
    p = fmaf(p, f, 1.3333558e-3f);
    p = fmaf(p, f, 9.6181291e-3f);
    p = fmaf(p, f, 5.5504109e-2f);
    p = fmaf(p, f, 2.4022651e-1f);
    p = fmaf(p, f, 6.9314718e-1f);
    p = fmaf(p, f, 1.0f);
    return __int_as_float(__float_as_int(p) + (ni << 23));
}

// LSTM pointwise update (validated: FMA-exp + 2 RCP).
__device__ __forceinline__ void lstm_point(float iv, float jv, float fv, float ov,
                                           float c, float& cn, float& hn) {
    float ef = exp_fma(-(fv + 1.0f));
    float ei = exp_fma(-iv);
    float ej = exp_fma(2.0f * jv);
    float eo = exp_fma(-ov);
    float Af = 1.0f + ef;
    float Ai = 1.0f + ei;
    float Aj = ej + 1.0f;
    float Nj = ej - 1.0f;
    float AiAj = Ai * Aj;
    float num = fmaf(c, AiAj, Nj * Af);
    cn = num * rcp_fast(Af * AiAj);
    float ec = exp_fma(2.0f * cn);
    hn = (ec - 1.0f) * rcp_fast((1.0f + eo) * (ec + 1.0f));
}

// ----------------- async copy helpers -----------------
__device__ __forceinline__ void cp16(uint32_t dst_smem, const void* src) {
    asm volatile("cp.async.cg.shared.global [%0], [%1], 16;"
                 :: "r"(dst_smem), "l"(src));
}
__device__ __forceinline__ void cp_commit() {
    asm volatile("cp.async.commit_group;");
}
template <int N>
__device__ __forceinline__ void cp_wait() {
    asm volatile("cp.async.wait_group %0;" :: "n"(N));
}

// mma.sync m16n8k16 bf16 (sm_80+ PTX, legal on plain sm_100 target)
__device__ __forceinline__ void mma16816(float& d0, float& d1, float& d2, float& d3,
                                         uint32_t a0, uint32_t a1, uint32_t a2,
                                         uint32_t a3, uint32_t b0, uint32_t b1) {
    asm volatile(
        "mma.sync.aligned.m16n8k16.row.col.f32.bf16.bf16.f32 "
        "{%0,%1,%2,%3}, {%4,%5,%6,%7}, {%8,%9}, {%0,%1,%2,%3};"
        : "+f"(d0), "+f"(d1), "+f"(d2), "+f"(d3)
        : "r"(a0), "r"(a1), "r"(a2), "r"(a3), "r"(b0), "r"(b1));
}

__device__ __forceinline__ void ldsm4(uint32_t& r0, uint32_t& r1,
                                      uint32_t& r2, uint32_t& r3, uint32_t a) {
    asm volatile("ldmatrix.sync.aligned.m8n8.x4.shared.b16 {%0,%1,%2,%3}, [%4];"
                 : "=r"(r0), "=r"(r1), "=r"(r2), "=r"(r3) : "r"(a));
}
__device__ __forceinline__ void ldsm2(uint32_t& r0, uint32_t& r1, uint32_t a) {
    asm volatile("ldmatrix.sync.aligned.m8n8.x2.shared.b16 {%0,%1}, [%2];"
                 : "=r"(r0), "=r"(r1) : "r"(a));
}

// ----------------- setup kernels -----------------

__global__ void detect_k(const unsigned int* __restrict__ mw) {
    int idx = blockIdx.x * blockDim.x + threadIdx.x;
    if (idx < TOKENS / 4) {
        if (mw[idx] > 1u) g_mask_is_byte = 1;   // benign race, same value
    }
}

// Permuted bf16 weights g_W[c'][k], c' = 4p+g (orig col g*300+p); bias too.
__global__ void wbuild_k(const float* __restrict__ Wx,
                         const float* __restrict__ Wh,
                         const float* __restrict__ bias) {
    int idx = blockIdx.x * blockDim.x + threadIdx.x;
    if (idx < NZP * KP) {
        int cp = idx / KP, k = idx % KP;
        float v = 0.f;
        if (cp < NZ && k < KTOT) {
            int p = cp >> 2, g = cp & 3;
            v = (k < EE) ? Wx[k * NZ + g * HH + p] : Wh[(k - EE) * NZ + g * HH + p];
        }
        g_W[idx] = __float2bfloat16(v);
    }
    if (idx < NZP) {
        float v = 0.f;
        if (idx < NZ) v = bias[(idx & 3) * HH + (idx >> 2)];
        g_biasP[idx] = v;
    }
}

// Gather embeddings as bf16 pairs into A images; 2 threads per token.
__global__ void gather_k(const int* __restrict__ tokens,
                         const float* __restrict__ emb) {
    int idx = blockIdx.x * blockDim.x + threadIdx.x;
    if (idx >= 2 * TOKENS) return;
    int tok_i = idx >> 1;
    int half = idx & 1;
    int b = tok_i / TT, t = tok_i - b * TT;
    const float* er = emb + (size_t)tokens[tok_i] * EE;
    uint32_t* dst = reinterpret_cast<uint32_t*>(
        g_A + ((size_t)t * BB + b) * KP);
    int q0 = half * 13;
    int q1 = half ? 25 : 13;
    for (int q = q0; q < q1; ++q) {
        __nv_bfloat162 p2 = __floats2bfloat162_rn(er[2 * q], er[2 * q + 1]);
        dst[q] = *reinterpret_cast<uint32_t*>(&p2);
    }
}

// --------- persistent kernel: all 120 LSTM steps -------------------------
// Per-ROW-GROUP barriers (17 blocks each, 8 independent groups): block
// (rb,cb) only consumes h produced by blocks (rb,*). Arrive/wait split:
// after the epilogue each block arrives (non-blocking), computes the
// h-independent x k-tiles of step t+1, and only then waits — hiding
// barrier propagation and the x load under real work.
__global__ __launch_bounds__(256) void lstm_persist_k() {
    extern __shared__ __align__(16) char dyn[];
    __shared__ float bias_s[GN];
    __shared__ unsigned base_phase_s;

    char* const As = dyn;                       // [128][720B]
    char* const Ws = dyn + AS_BYTES;            // [72][720B]
    const uint32_t sA = (uint32_t)__cvta_generic_to_shared(As);
    const uint32_t sW = (uint32_t)__cvta_generic_to_shared(Ws);

    const int tid = threadIdx.x;
    const int warp = tid >> 5;
    const int lane = tid & 31;
    const int g = lane >> 2;
    const int tig = lane & 3;
    const int rb = blockIdx.x;
    const int cbk = blockIdx.y;
    const int pblk = cbk * POSB;
    const int m0 = warp * 16;

    // Entry phase read precedes this block's first arrival, hence precedes
    // the group's first phase bump: all group members see the same base.
    if (tid == 0) base_phase_s = *(volatile unsigned*)&g_bars[rb].phase;

    auto load_cols = [&](const char* gbase, int c0, int c1) {
        const int span = c1 - c0;
        for (int i = tid; i < GM * span; i += 256) {
            int r = i / span, c = c0 + i - (i / span) * span;
            cp16(sA + r * AS_STRIDE + c * 16, gbase + r * (KP * 2) + c * 16);
        }
    };

    // initial loads: group0 = W + bias + A x-cols; groups 1..4 = A h-cols
    {
        const char* gWb = reinterpret_cast<const char*>(g_W + (size_t)cbk * GN * KP);
        for (int i = tid; i < WCH; i += 256) {
            int r = i / 44, c = i - (i / 44) * 44;
            cp16(sW + r * AS_STRIDE + c * 16, gWb + r * (KP * 2) + c * 16);
        }
        const char* gAb = reinterpret_cast<const char*>(g_A + ((size_t)rb * GM) * KP);
        load_cols(gAb, 0, 6);  cp_commit();
        load_cols(gAb, 6, 16); cp_commit();
        load_cols(gAb, 16, 26); cp_commit();
        load_cols(gAb, 26, 36); cp_commit();
        load_cols(gAb, 36, 44); cp_commit();
        if (tid < GN) bias_s[tid] = g_biasP[cbk * GN + tid];
    }
    __syncthreads();
    const unsigned base_phase = base_phase_s;

    // ldmatrix lane addresses (fixed across steps; +kk*32 per k-tile)
    const int quad = lane >> 3, lr = lane & 7;
    const uint32_t aBase = sA + (uint32_t)(m0 + (quad & 1) * 8 + lr) * AS_STRIDE
                         + (uint32_t)(quad >> 1) * 16;
    uint32_t bBase[5];
#pragma unroll
    for (int jp = 0; jp < 4; ++jp)
        bBase[jp] = sW + (uint32_t)((2 * jp + (lane >> 4)) * 8 + lr) * AS_STRIDE
                  + (uint32_t)((lane >> 3) & 1) * 16;
    {
        int l2 = lane & 15;
        bBase[4] = sW + (uint32_t)(64 + (l2 & 7)) * AS_STRIDE
                 + (uint32_t)(l2 >> 3) * 16;
    }
    const int rowlo = rb * GM + m0 + g;

    float creg[NT];
#pragma unroll
    for (int j = 0; j < NT; ++j) creg[j] = 0.f;

    float acc[NT][4];

    auto zero_acc = [&]() {
#pragma unroll
        for (int j = 0; j < NT; ++j)
#pragma unroll
            for (int e = 0; e < 4; ++e) acc[j][e] = 0.f;
    };
    auto mma_tiles = [&](int kk0, int kk1) {
        for (int kk = kk0; kk < kk1; ++kk) {
            const uint32_t ko = (uint32_t)kk * 32;
            uint32_t a0, a1, a2, a3;
            ldsm4(a0, a1, a2, a3, aBase + ko);
#pragma unroll
            for (int jp = 0; jp < 4; ++jp) {
                uint32_t b0, b1, b2, b3;
                ldsm4(b0, b1, b2, b3, bBase[jp] + ko);
                mma16816(acc[2 * jp][0], acc[2 * jp][1],
                         acc[2 * jp][2], acc[2 * jp][3],
                         a0, a1, a2, a3, b0, b1);
                mma16816(acc[2 * jp + 1][0], acc[2 * jp + 1][1],
                         acc[2 * jp + 1][2], acc[2 * jp + 1][3],
                         a0, a1, a2, a3, b2, b3);
            }
            uint32_t c0, c1;
            ldsm2(c0, c1, bBase[4] + ko);
            mma16816(acc[8][0], acc[8][1], acc[8][2], acc[8][3],
                     a0, a1, a2, a3, c0, c1);
        }
    };

    // prologue: x k-tiles of t=0 (group0 = oldest of 5 pending -> wait<4>)
    zero_acc();
    cp_wait<4>();
    __syncthreads();
    mma_tiles(0, 3);

    for (int t = 0; t < TT; ++t) {
        // h stages (4 pipelined cp.async groups pending at this point)
        cp_wait<3>(); __syncthreads(); mma_tiles(3, 8);    // k48..127
        cp_wait<2>(); __syncthreads(); mma_tiles(8, 13);   // k128..207
        cp_wait<1>(); __syncthreads(); mma_tiles(13, 18);  // k208..287
        cp_wait<0>(); __syncthreads(); mma_tiles(18, 22);  // k288..351
        __syncthreads();   // all warps done with As before x-prefetch

        const bool more = (t + 1 < TT);
        if (more) {
            const char* gAb = reinterpret_cast<const char*>(
                g_A + ((size_t)(t + 1) * BB + rb * GM) * KP);
            load_cols(gAb, 0, 6);      // x cols of t+1 (independent of h)
            cp_commit();
        }

        // ---- epilogue: regroup gates via shfl, LSTM update, h -> A[t+1] ----
        __nv_bfloat16* gAn = g_A + ((size_t)(t + 1) * BB) * KP;
#pragma unroll
        for (int j = 0; j < NT; ++j) {
            float d0 = acc[j][0], d1 = acc[j][1], d2 = acc[j][2], d3 = acc[j][3];
            float x0 = __shfl_xor_sync(0xffffffffu, d0, 1);
            float x1 = __shfl_xor_sync(0xffffffffu, d1, 1);
            float x2 = __shfl_xor_sync(0xffffffffu, d2, 1);
            float x3 = __shfl_xor_sync(0xffffffffu, d3, 1);
            const bool odd = (tig & 1);
            float iv = odd ? x2 : d0;
            float jv = odd ? x3 : d1;
            float fv = odd ? d2 : x0;
            float ov = odd ? d3 : x1;
            int pl = 2 * j + (tig >> 1);
            int p = pblk + pl;
            int b = rowlo + (odd ? 8 : 0);
            iv += bias_s[4 * pl + 0];
            jv += bias_s[4 * pl + 1];
            fv += bias_s[4 * pl + 2];
            ov += bias_s[4 * pl + 3];
            float hn = 0.f;
            if (p < HH) {
                float cn;
                lstm_point(iv, jv, fv, ov, creg[j], cn, hn);
                creg[j] = cn;
            }
            float hp = __shfl_xor_sync(0xffffffffu, hn, 2);
            if (!(tig & 2) && p < HH) {
                __nv_bfloat162 hb = __floats2bfloat162_rn(hn, hp);
                *reinterpret_cast<uint32_t*>(&gAn[(size_t)b * KP + EE + p])
                    = *reinterpret_cast<uint32_t*>(&hb);
            }
        }

        if (more) {
            // ---- arrive (non-blocking) on this row-group's barrier ----
            __threadfence();
            __syncthreads();
            if (tid == 0) {
                if (atomicAdd(&g_bars[rb].cnt, 1u) == NGRP - 1) {
                    atomicExch(&g_bars[rb].cnt, 0u);
                    __threadfence();
                    atomicAdd(&g_bars[rb].phase, 1u);
                }
            }

            // ---- hide barrier latency: x k-tiles of t+1 ----
            zero_acc();
            cp_wait<0>();          // x prefetch resident
            __syncthreads();
            mma_tiles(0, 3);

            // ---- wait for group peers' h(t+1), then issue h loads ----
            if (tid == 0) {
                unsigned tgt = (unsigned)(t + 1);
                while ((*(volatile unsigned*)&g_bars[rb].phase) - base_phase < tgt) {}
            }
            __syncthreads();
            const char* gAb = reinterpret_cast<const char*>(
                g_A + ((size_t)(t + 1) * BB + rb * GM) * KP);
            load_cols(gAb, 6, 16);  cp_commit();
            load_cols(gAb, 16, 26); cp_commit();
            load_cols(gAb, 26, 36); cp_commit();
            load_cols(gAb, 36, 44); cp_commit();
        }
    }
}

// ----------------- CE: projection + log-softmax + masked sum ----------------
// h for step t read as bf16 from A image t+1 (k = 50..349), contiguous/token.
__global__ void ce_k(const float* __restrict__ U, const float* __restrict__ b2,
                     const int* __restrict__ labels,
                     const void* __restrict__ maskp)
{
    __shared__ float Us[HH * CC];
    __shared__ float b2s[CC];
    __shared__ double sd[CE_TB];
    __shared__ int    sc[CE_TB];

    const int tid = threadIdx.x;
    const int t = blockIdx.x >> 3;
    const int b = ((blockIdx.x & 7) << 7) + tid;

    for (int i = tid; i < HH * CC; i += CE_TB) Us[i] = U[i];
    if (tid < CC) b2s[tid] = b2[tid];
    __syncthreads();

    float s0 = b2s[0], s1 = b2s[1], s2 = b2s[2], s3 = b2s[3], s4 = b2s[4];
    const uint32_t* hp = reinterpret_cast<const uint32_t*>(
        g_A + ((size_t)(t + 1) * BB + b) * KP + EE);
#pragma unroll 2
    for (int q = 0; q < HH / 2; ++q) {
        __nv_bfloat162 h2 = *reinterpret_cast<const __nv_bfloat162*>(&hp[q]);
        float h0 = __bfloat162float(h2.x);
        float h1 = __bfloat162float(h2.y);
        const float* u0 = &Us[(2 * q) * CC];
        const float* u1 = &Us[(2 * q + 1) * CC];
        s0 += h0 * u0[0] + h1 * u1[0];
        s1 += h0 * u0[1] + h1 * u1[1];
        s2 += h0 * u0[2] + h1 * u1[2];
        s3 += h0 * u0[3] + h1 * u1[3];
        s4 += h0 * u0[4] + h1 * u1[4];
    }

    float m = fmaxf(fmaxf(fmaxf(s0, s1), fmaxf(s2, s3)), s4);
    float sum = __expf(s0 - m) + __expf(s1 - m) + __expf(s2 - m)
              + __expf(s3 - m) + __expf(s4 - m);
    float lse = m + __logf(sum);
    int lab = labels[b * TT + t];
    float lc = (lab == 0) ? s0 : (lab == 1) ? s1 : (lab == 2) ? s2
             : (lab == 3) ? s3 : s4;
    float ce = lse - lc;
    int mk;
    if (g_mask_is_byte) mk = (((const unsigned char*)maskp)[b * TT + t] != 0);
    else                mk = (((const int*)maskp)[b * TT + t] != 0);

    sd[tid] = mk ? (double)ce : 0.0;
    sc[tid] = mk;
    __syncthreads();
    for (int off = CE_TB / 2; off; off >>= 1) {
        if (tid < off) { sd[tid] += sd[tid + off]; sc[tid] += sc[tid + off]; }
        __syncthreads();
    }
    if (tid == 0) { g_bsum[blockIdx.x] = sd[0]; g_bcnt[blockIdx.x] = sc[0]; }
}

__global__ void fin_k(float* out) {
    __shared__ double sd[256];
    __shared__ int    sc[256];
    int i = threadIdx.x;
    double s = 0.0; int c = 0;
    for (int j = i; j < CE_BLOCKS; j += 256) { s += g_bsum[j]; c += g_bcnt[j]; }
    sd[i] = s; sc[i] = c;
    __syncthreads();
    for (int off = 128; off; off >>= 1) {
        if (i < off) { sd[i] += sd[i + off]; sc[i] += sc[i + off]; }
        __syncthreads();
    }
    if (i == 0) out[0] = (float)(sd[0] / (double)sc[0]);
}

// ----------------- launcher -----------------
extern "C" void kernel_launch(void* const* d_in, const int* in_sizes, int n_in,
                              void* d_out, int out_size)
{
    const int*   tokens = (const int*)d_in[0];
    const int*   labels = (const int*)d_in[1];
    const void*  mask   = d_in[2];
    const float* emb    = (const float*)d_in[3];
    const float* Wx     = (const float*)d_in[4];
    const float* Wh     = (const float*)d_in[5];
    const float* bias   = (const float*)d_in[6];
    const float* U      = (const float*)d_in[7];
    const float* b2     = (const float*)d_in[8];
    float* out = (float*)d_out;

    static int smem_set = 0;
    if (!smem_set) {
        cudaFuncSetAttribute(lstm_persist_k,
                             cudaFuncAttributeMaxDynamicSharedMemorySize,
                             DYN_BYTES);
        smem_set = 1;
    }

    detect_k<<<(TOKENS / 4 + 255) / 256, 256>>>((const unsigned int*)mask);
    wbuild_k<<<(NZP * KP + 255) / 256, 256>>>(Wx, Wh, bias);
    gather_k<<<(2 * TOKENS + 255) / 256, 256>>>(tokens, emb);

    dim3 ggrid(BB / GM, NZP / GN);                 // (8, 17) = 136 blocks
    lstm_persist_k<<<ggrid, 256, DYN_BYTES>>>();   // launch #3 (profiled)

    ce_k<<<CE_BLOCKS, CE_TB>>>(U, b2, labels, mask);
    fin_k<<<1, 256>>>(out);
    (void)in_sizes; (void)n_in; (void)out_size;
}

// round 16
// speedup vs baseline: 1.0958x; 1.0958x over previous
#include <cuda_runtime.h>
#include <cuda_bf16.h>
#include <cstdint>
#include <math.h>

// Problem constants
constexpr int BB = 1024;
constexpr int TT = 120;
constexpr int EE = 50;
constexpr int HH = 300;
constexpr int CC = 5;
constexpr int KTOT = EE + HH;        // 350
constexpr int KP = 352;              // K padded (22 * 16), cols 350/351 zero
constexpr int NZ = 4 * HH;           // 1200
constexpr int NZP = 1224;            // 17 * 72 permuted cols

// Tiling: grid (8, 17) = 136 blocks (one wave, 1 block/SM), 512 threads.
// Warp w -> (m-tile = w>>1, n-half = w&1). n-half 0: n-tiles {0..3, 8};
// n-half 1: n-tiles {4..7}.
constexpr int GM = 128;
constexpr int GN = 72;               // 18 positions * 4 gates
constexpr int POSB = 18;
constexpr int NGRP = 17;             // blocks per row-group (same rb)
constexpr int NTHR = 512;

// smem: A[128][720B] + W[72][720B] (720B row stride, conflict-free)
constexpr int AS_STRIDE = 720;
constexpr int AS_BYTES = GM * AS_STRIDE;       // 92160
constexpr int WS_BYTES = GN * AS_STRIDE;       // 51840
constexpr int DYN_BYTES = AS_BYTES + WS_BYTES; // 144000
constexpr int WCH = GN * 44;         // W 16B chunks

// CE kernel
constexpr int TOKENS = BB * TT;
constexpr int CE_TB = 128;
constexpr int CE_BLOCKS = TOKENS / CE_TB;      // 960

// ----------------- device scratch (no cudaMalloc allowed) -----------------
__device__ __align__(16) __nv_bfloat16 g_A[(TT + 1) * BB * KP]; // 87.2 MB
__device__ __align__(16) __nv_bfloat16 g_W[NZP * KP];           // 0.86 MB
__device__ float    g_biasP[NZP];
__device__ double   g_bsum[CE_BLOCKS];
__device__ int      g_bcnt[CE_BLOCKS];
__device__ int      g_mask_is_byte;

// Per-row-group barriers, 256B padded (avoid L2 hash bit-7 pair-collide).
struct __align__(256) GroupBar { unsigned cnt; unsigned phase; unsigned pad[62]; };
__device__ GroupBar g_bars[8];       // cnt returns to 0; phase monotonic

// ----------------- scalar helpers -----------------
__device__ __forceinline__ float rcp_fast(float x) {
    float y;
    asm("rcp.approx.f32 %0, %1;" : "=f"(y) : "f"(x));
    return y;
}

// exp(x) with zero MUFU: FMA-only range reduction + 2^f poly + exponent add.
__device__ __forceinline__ float exp_fma(float x) {
    float x2 = x * 1.4426950408889634f;
    x2 = fminf(fmaxf(x2, -30.0f), 30.0f);
    float biased = x2 + 12582912.0f;            // 1.5 * 2^23
    int   ni = __float_as_int(biased) - 0x4B400000;
    float n = biased - 12582912.0f;
    float f = x2 - n;
    float p = 1.5403530e-4f;
    p = fmaf(p, f, 1.3333558e-3f);
    p = fmaf(p, f, 9.6181291e-3f);
    p = fmaf(p, f, 5.5504109e-2f);
    p = fmaf(p, f, 2.4022651e-1f);
    p = fmaf(p, f, 6.9314718e-1f);
    p = fmaf(p, f, 1.0f);
    return __int_as_float(__float_as_int(p) + (ni << 23));
}

// LSTM pointwise update (validated: FMA-exp + 2 RCP).
__device__ __forceinline__ void lstm_point(float iv, float jv, float fv, float ov,
                                           float c, float& cn, float& hn) {
    float ef = exp_fma(-(fv + 1.0f));
    float ei = exp_fma(-iv);
    float ej = exp_fma(2.0f * jv);
    float eo = exp_fma(-ov);
    float Af = 1.0f + ef;
    float Ai = 1.0f + ei;
    float Aj = ej + 1.0f;
    float Nj = ej - 1.0f;
    float AiAj = Ai * Aj;
    float num = fmaf(c, AiAj, Nj * Af);
    cn = num * rcp_fast(Af * AiAj);
    float ec = exp_fma(2.0f * cn);
    hn = (ec - 1.0f) * rcp_fast((1.0f + eo) * (ec + 1.0f));
}

// ----------------- async copy helpers -----------------
__device__ __forceinline__ void cp16(uint32_t dst_smem, const void* src) {
    asm volatile("cp.async.cg.shared.global [%0], [%1], 16;"
                 :: "r"(dst_smem), "l"(src));
}
__device__ __forceinline__ void cp_commit() {
    asm volatile("cp.async.commit_group;");
}
template <int N>
__device__ __forceinline__ void cp_wait() {
    asm volatile("cp.async.wait_group %0;" :: "n"(N));
}

// mma.sync m16n8k16 bf16 (sm_80+ PTX, legal on plain sm_100 target)
__device__ __forceinline__ void mma16816(float& d0, float& d1, float& d2, float& d3,
                                         uint32_t a0, uint32_t a1, uint32_t a2,
                                         uint32_t a3, uint32_t b0, uint32_t b1) {
    asm volatile(
        "mma.sync.aligned.m16n8k16.row.col.f32.bf16.bf16.f32 "
        "{%0,%1,%2,%3}, {%4,%5,%6,%7}, {%8,%9}, {%0,%1,%2,%3};"
        : "+f"(d0), "+f"(d1), "+f"(d2), "+f"(d3)
        : "r"(a0), "r"(a1), "r"(a2), "r"(a3), "r"(b0), "r"(b1));
}

__device__ __forceinline__ void ldsm4(uint32_t& r0, uint32_t& r1,
                                      uint32_t& r2, uint32_t& r3, uint32_t a) {
    asm volatile("ldmatrix.sync.aligned.m8n8.x4.shared.b16 {%0,%1,%2,%3}, [%4];"
                 : "=r"(r0), "=r"(r1), "=r"(r2), "=r"(r3) : "r"(a));
}
__device__ __forceinline__ void ldsm2(uint32_t& r0, uint32_t& r1, uint32_t a) {
    asm volatile("ldmatrix.sync.aligned.m8n8.x2.shared.b16 {%0,%1}, [%2];"
                 : "=r"(r0), "=r"(r1) : "r"(a));
}

// ----------------- setup kernels -----------------

__global__ void detect_k(const unsigned int* __restrict__ mw) {
    int idx = blockIdx.x * blockDim.x + threadIdx.x;
    if (idx < TOKENS / 4) {
        if (mw[idx] > 1u) g_mask_is_byte = 1;   // benign race, same value
    }
}

// Permuted bf16 weights g_W[c'][k], c' = 4p+g (orig col g*300+p); bias too.
__global__ void wbuild_k(const float* __restrict__ Wx,
                         const float* __restrict__ Wh,
                         const float* __restrict__ bias) {
    int idx = blockIdx.x * blockDim.x + threadIdx.x;
    if (idx < NZP * KP) {
        int cp = idx / KP, k = idx % KP;
        float v = 0.f;
        if (cp < NZ && k < KTOT) {
            int p = cp >> 2, g = cp & 3;
            v = (k < EE) ? Wx[k * NZ + g * HH + p] : Wh[(k - EE) * NZ + g * HH + p];
        }
        g_W[idx] = __float2bfloat16(v);
    }
    if (idx < NZP) {
        float v = 0.f;
        if (idx < NZ) v = bias[(idx & 3) * HH + (idx >> 2)];
        g_biasP[idx] = v;
    }
}

// Gather embeddings as bf16 pairs into A images; 2 threads per token.
__global__ void gather_k(const int* __restrict__ tokens,
                         const float* __restrict__ emb) {
    int idx = blockIdx.x * blockDim.x + threadIdx.x;
    if (idx >= 2 * TOKENS) return;
    int tok_i = idx >> 1;
    int half = idx & 1;
    int b = tok_i / TT, t = tok_i - b * TT;
    const float* er = emb + (size_t)tokens[tok_i] * EE;
    uint32_t* dst = reinterpret_cast<uint32_t*>(
        g_A + ((size_t)t * BB + b) * KP);
    int q0 = half * 13;
    int q1 = half ? 25 : 13;
    for (int q = q0; q < q1; ++q) {
        __nv_bfloat162 p2 = __floats2bfloat162_rn(er[2 * q], er[2 * q + 1]);
        dst[q] = *reinterpret_cast<uint32_t*>(&p2);
    }
}

// --------- persistent kernel: all 120 LSTM steps, 512 threads --------------
// 16 warps (4/SMSP) to cover ldsm/HMMA/shfl/exp latency chains. Warp w:
// m-tile w>>1, n-half w&1 (n-half 0: n-tiles {0..3,8}; n-half 1: {4..7}).
// Per-row-group barriers + arrive/x-mma/wait split as in R15.
__global__ __launch_bounds__(NTHR) void lstm_persist_k() {
    extern __shared__ __align__(16) char dyn[];
    __shared__ float bias_s[GN];
    __shared__ unsigned base_phase_s;

    char* const As = dyn;                       // [128][720B]
    char* const Ws = dyn + AS_BYTES;            // [72][720B]
    const uint32_t sA = (uint32_t)__cvta_generic_to_shared(As);
    const uint32_t sW = (uint32_t)__cvta_generic_to_shared(Ws);

    const int tid = threadIdx.x;
    const int warp = tid >> 5;
    const int lane = tid & 31;
    const int g = lane >> 2;
    const int tig = lane & 3;
    const int mt = warp >> 1;        // m-tile 0..7
    const int nhalf = warp & 1;      // n-half
    const int rb = blockIdx.x;
    const int cbk = blockIdx.y;
    const int pblk = cbk * POSB;
    const int m0 = mt * 16;

    if (tid == 0) base_phase_s = *(volatile unsigned*)&g_bars[rb].phase;

    auto load_cols = [&](const char* gbase, int c0, int c1) {
        const int span = c1 - c0;
        for (int i = tid; i < GM * span; i += NTHR) {
            int r = i / span, c = c0 + i - (i / span) * span;
            cp16(sA + r * AS_STRIDE + c * 16, gbase + r * (KP * 2) + c * 16);
        }
    };

    // initial loads: group0 = W + bias + A x-cols; groups 1..4 = A h-cols
    {
        const char* gWb = reinterpret_cast<const char*>(g_W + (size_t)cbk * GN * KP);
        for (int i = tid; i < WCH; i += NTHR) {
            int r = i / 44, c = i - (i / 44) * 44;
            cp16(sW + r * AS_STRIDE + c * 16, gWb + r * (KP * 2) + c * 16);
        }
        const char* gAb = reinterpret_cast<const char*>(g_A + ((size_t)rb * GM) * KP);
        load_cols(gAb, 0, 6);  cp_commit();
        load_cols(gAb, 6, 16); cp_commit();
        load_cols(gAb, 16, 26); cp_commit();
        load_cols(gAb, 26, 36); cp_commit();
        load_cols(gAb, 36, 44); cp_commit();
        if (tid < GN) bias_s[tid] = g_biasP[cbk * GN + tid];
    }
    __syncthreads();
    const unsigned base_phase = base_phase_s;

    // ldmatrix lane addresses (fixed across steps; +kk*32 per k-tile)
    const int quad = lane >> 3, lr = lane & 7;
    const uint32_t aBase = sA + (uint32_t)(m0 + (quad & 1) * 8 + lr) * AS_STRIDE
                         + (uint32_t)(quad >> 1) * 16;
    // B pair bases: this warp's jp = 2*nhalf + u, u = 0,1
    uint32_t bB[2];
#pragma unroll
    for (int u = 0; u < 2; ++u) {
        int jp = 2 * nhalf + u;
        bB[u] = sW + (uint32_t)((2 * jp + (lane >> 4)) * 8 + lr) * AS_STRIDE
              + (uint32_t)((lane >> 3) & 1) * 16;
    }
    uint32_t bB4;
    {
        int l2 = lane & 15;
        bB4 = sW + (uint32_t)(64 + (l2 & 7)) * AS_STRIDE + (uint32_t)(l2 >> 3) * 16;
    }
    const int rowlo = rb * GM + m0 + g;

    float creg[5];
#pragma unroll
    for (int u = 0; u < 5; ++u) creg[u] = 0.f;

    float acc[5][4];

    auto zero_acc = [&]() {
#pragma unroll
        for (int u = 0; u < 5; ++u)
#pragma unroll
            for (int e = 0; e < 4; ++e) acc[u][e] = 0.f;
    };
    auto mma_tiles = [&](int kk0, int kk1) {
        for (int kk = kk0; kk < kk1; ++kk) {
            const uint32_t ko = (uint32_t)kk * 32;
            uint32_t a0, a1, a2, a3;
            ldsm4(a0, a1, a2, a3, aBase + ko);
#pragma unroll
            for (int u = 0; u < 2; ++u) {
                uint32_t b0, b1, b2, b3;
                ldsm4(b0, b1, b2, b3, bB[u] + ko);
                mma16816(acc[2 * u][0], acc[2 * u][1],
                         acc[2 * u][2], acc[2 * u][3],
                         a0, a1, a2, a3, b0, b1);
                mma16816(acc[2 * u + 1][0], acc[2 * u + 1][1],
                         acc[2 * u + 1][2], acc[2 * u + 1][3],
                         a0, a1, a2, a3, b2, b3);
            }
            if (nhalf == 0) {
                uint32_t c0, c1;
                ldsm2(c0, c1, bB4 + ko);
                mma16816(acc[4][0], acc[4][1], acc[4][2], acc[4][3],
                         a0, a1, a2, a3, c0, c1);
            }
        }
    };

    // prologue: x k-tiles of t=0 (group0 = oldest of 5 pending -> wait<4>)
    zero_acc();
    cp_wait<4>();
    __syncthreads();
    mma_tiles(0, 3);

    for (int t = 0; t < TT; ++t) {
        cp_wait<3>(); __syncthreads(); mma_tiles(3, 8);    // k48..127
        cp_wait<2>(); __syncthreads(); mma_tiles(8, 13);   // k128..207
        cp_wait<1>(); __syncthreads(); mma_tiles(13, 18);  // k208..287
        cp_wait<0>(); __syncthreads(); mma_tiles(18, 22);  // k288..351
        __syncthreads();   // all warps done with As before x-prefetch

        const bool more = (t + 1 < TT);
        if (more) {
            const char* gAb = reinterpret_cast<const char*>(
                g_A + ((size_t)(t + 1) * BB + rb * GM) * KP);
            load_cols(gAb, 0, 6);      // x cols of t+1 (independent of h)
            cp_commit();
        }

        // ---- epilogue: regroup gates via shfl, LSTM update, h -> A[t+1] ----
        __nv_bfloat16* gAn = g_A + ((size_t)(t + 1) * BB) * KP;
#pragma unroll
        for (int u = 0; u < 5; ++u) {
            if (nhalf == 1 && u == 4) break;
            const int j = (nhalf == 0) ? ((u < 4) ? u : 8) : (4 + u);
            float d0 = acc[u][0], d1 = acc[u][1], d2 = acc[u][2], d3 = acc[u][3];
            float x0 = __shfl_xor_sync(0xffffffffu, d0, 1);
            float x1 = __shfl_xor_sync(0xffffffffu, d1, 1);
            float x2 = __shfl_xor_sync(0xffffffffu, d2, 1);
            float x3 = __shfl_xor_sync(0xffffffffu, d3, 1);
            const bool odd = (tig & 1);
            float iv = odd ? x2 : d0;
            float jv = odd ? x3 : d1;
            float fv = odd ? d2 : x0;
            float ov = odd ? d3 : x1;
            int pl = 2 * j + (tig >> 1);
            int p = pblk + pl;
            int b = rowlo + (odd ? 8 : 0);
            iv += bias_s[4 * pl + 0];
            jv += bias_s[4 * pl + 1];
            fv += bias_s[4 * pl + 2];
            ov += bias_s[4 * pl + 3];
            float hn = 0.f;
            if (p < HH) {
                float cn;
                lstm_point(iv, jv, fv, ov, creg[u], cn, hn);
                creg[u] = cn;
            }
            float hp = __shfl_xor_sync(0xffffffffu, hn, 2);
            if (!(tig & 2) && p < HH) {
                __nv_bfloat162 hb = __floats2bfloat162_rn(hn, hp);
                *reinterpret_cast<uint32_t*>(&gAn[(size_t)b * KP + EE + p])
                    = *reinterpret_cast<uint32_t*>(&hb);
            }
        }

        if (more) {
            // ---- arrive (non-blocking) on this row-group's barrier ----
            __threadfence();
            __syncthreads();
            if (tid == 0) {
                if (atomicAdd(&g_bars[rb].cnt, 1u) == NGRP - 1) {
                    atomicExch(&g_bars[rb].cnt, 0u);
                    __threadfence();
                    atomicAdd(&g_bars[rb].phase, 1u);
                }
            }

            // ---- hide barrier latency: x k-tiles of t+1 ----
            zero_acc();
            cp_wait<0>();          // x prefetch resident
            __syncthreads();
            mma_tiles(0, 3);

            // ---- wait for group peers' h(t+1), then issue h loads ----
            if (tid == 0) {
                unsigned tgt = (unsigned)(t + 1);
                while ((*(volatile unsigned*)&g_bars[rb].phase) - base_phase < tgt) {}
            }
            __syncthreads();
            const char* gAb = reinterpret_cast<const char*>(
                g_A + ((size_t)(t + 1) * BB + rb * GM) * KP);
            load_cols(gAb, 6, 16);  cp_commit();
            load_cols(gAb, 16, 26); cp_commit();
            load_cols(gAb, 26, 36); cp_commit();
            load_cols(gAb, 36, 44); cp_commit();
        }
    }
}

// ----------------- CE: projection + log-softmax + masked sum ----------------
// h for step t read as bf16 from A image t+1 (k = 50..349), contiguous/token.
__global__ void ce_k(const float* __restrict__ U, const float* __restrict__ b2,
                     const int* __restrict__ labels,
                     const void* __restrict__ maskp)
{
    __shared__ float Us[HH * CC];
    __shared__ float b2s[CC];
    __shared__ double sd[CE_TB];
    __shared__ int    sc[CE_TB];

    const int tid = threadIdx.x;
    const int t = blockIdx.x >> 3;
    const int b = ((blockIdx.x & 7) << 7) + tid;

    for (int i = tid; i < HH * CC; i += CE_TB) Us[i] = U[i];
    if (tid < CC) b2s[tid] = b2[tid];
    __syncthreads();

    float s0 = b2s[0], s1 = b2s[1], s2 = b2s[2], s3 = b2s[3], s4 = b2s[4];
    const uint32_t* hp = reinterpret_cast<const uint32_t*>(
        g_A + ((size_t)(t + 1) * BB + b) * KP + EE);
#pragma unroll 2
    for (int q = 0; q < HH / 2; ++q) {
        __nv_bfloat162 h2 = *reinterpret_cast<const __nv_bfloat162*>(&hp[q]);
        float h0 = __bfloat162float(h2.x);
        float h1 = __bfloat162float(h2.y);
        const float* u0 = &Us[(2 * q) * CC];
        const float* u1 = &Us[(2 * q + 1) * CC];
        s0 += h0 * u0[0] + h1 * u1[0];
        s1 += h0 * u0[1] + h1 * u1[1];
        s2 += h0 * u0[2] + h1 * u1[2];
        s3 += h0 * u0[3] + h1 * u1[3];
        s4 += h0 * u0[4] + h1 * u1[4];
    }

    float m = fmaxf(fmaxf(fmaxf(s0, s1), fmaxf(s2, s3)), s4);
    float sum = __expf(s0 - m) + __expf(s1 - m) + __expf(s2 - m)
              + __expf(s3 - m) + __expf(s4 - m);
    float lse = m + __logf(sum);
    int lab = labels[b * TT + t];
    float lc = (lab == 0) ? s0 : (lab == 1) ? s1 : (lab == 2) ? s2
             : (lab == 3) ? s3 : s4;
    float ce = lse - lc;
    int mk;
    if (g_mask_is_byte) mk = (((const unsigned char*)maskp)[b * TT + t] != 0);
    else                mk = (((const int*)maskp)[b * TT + t] != 0);

    sd[tid] = mk ? (double)ce : 0.0;
    sc[tid] = mk;
    __syncthreads();
    for (int off = CE_TB / 2; off; off >>= 1) {
        if (tid < off) { sd[tid] += sd[tid + off]; sc[tid] += sc[tid + off]; }
        __syncthreads();
    }
    if (tid == 0) { g_bsum[blockIdx.x] = sd[0]; g_bcnt[blockIdx.x] = sc[0]; }
}

__global__ void fin_k(float* out) {
    __shared__ double sd[256];
    __shared__ int    sc[256];
    int i = threadIdx.x;
    double s = 0.0; int c = 0;
    for (int j = i; j < CE_BLOCKS; j += 256) { s += g_bsum[j]; c += g_bcnt[j]; }
    sd[i] = s; sc[i] = c;
    __syncthreads();
    for (int off = 128; off; off >>= 1) {
        if (i < off) { sd[i] += sd[i + off]; sc[i] += sc[i + off]; }
        __syncthreads();
    }
    if (i == 0) out[0] = (float)(sd[0] / (double)sc[0]);
}

// ----------------- launcher -----------------
extern "C" void kernel_launch(void* const* d_in, const int* in_sizes, int n_in,
                              void* d_out, int out_size)
{
    const int*   tokens = (const int*)d_in[0];
    const int*   labels = (const int*)d_in[1];
    const void*  mask   = d_in[2];
    const float* emb    = (const float*)d_in[3];
    const float* Wx     = (const float*)d_in[4];
    const float* Wh     = (const float*)d_in[5];
    const float* bias   = (const float*)d_in[6];
    const float* U      = (const float*)d_in[7];
    const float* b2     = (const float*)d_in[8];
    float* out = (float*)d_out;

    static int smem_set = 0;
    if (!smem_set) {
        cudaFuncSetAttribute(lstm_persist_k,
                             cudaFuncAttributeMaxDynamicSharedMemorySize,
                             DYN_BYTES);
        smem_set = 1;
    }

    detect_k<<<(TOKENS / 4 + 255) / 256, 256>>>((const unsigned int*)mask);
    wbuild_k<<<(NZP * KP + 255) / 256, 256>>>(Wx, Wh, bias);
    gather_k<<<(2 * TOKENS + 255) / 256, 256>>>(tokens, emb);

    dim3 ggrid(BB / GM, NZP / GN);                 // (8, 17) = 136 blocks
    lstm_persist_k<<<ggrid, NTHR, DYN_BYTES>>>();  // launch #3 (profiled)

    ce_k<<<CE_BLOCKS, CE_TB>>>(U, b2, labels, mask);
    fin_k<<<1, 256>>>(out);
    (void)in_sizes; (void)n_in; (void)out_size;
}

// round 17
// speedup vs baseline: 1.1081x; 1.0112x over previous
#include <cuda_runtime.h>
#include <cuda_bf16.h>
#include <cstdint>
#include <math.h>

// Problem constants
constexpr int BB = 1024;
constexpr int TT = 120;
constexpr int EE = 50;
constexpr int HH = 300;
constexpr int CC = 5;
constexpr int KTOT = EE + HH;        // 350
constexpr int KP = 352;              // K padded (22 * 16), cols 350/351 zero
constexpr int NZ = 4 * HH;           // 1200
constexpr int NZP = 1224;            // 17 * 72 permuted cols

// Tiling: grid (8, 17) = 136 blocks (one wave, 1 block/SM), 768 threads.
// Warp w -> (m-tile = w % 8, n-group = w / 8). n-group ng owns n-tiles
// {3ng, 3ng+1} (ldsm4 pair) + {3ng+2} (ldsm2 single).
constexpr int GM = 128;
constexpr int GN = 72;               // 18 positions * 4 gates
constexpr int POSB = 18;
constexpr int NGRP = 17;             // blocks per row-group (same rb)
constexpr int NTHR = 768;

// smem: A[128][720B] + W[72][720B] (720B row stride, conflict-free)
constexpr int AS_STRIDE = 720;
constexpr int AS_BYTES = GM * AS_STRIDE;       // 92160
constexpr int WS_BYTES = GN * AS_STRIDE;       // 51840
constexpr int DYN_BYTES = AS_BYTES + WS_BYTES; // 144000
constexpr int WCH = GN * 44;         // W 16B chunks

// CE kernel
constexpr int TOKENS = BB * TT;
constexpr int CE_TB = 128;
constexpr int CE_BLOCKS = TOKENS / CE_TB;      // 960

// ----------------- device scratch (no cudaMalloc allowed) -----------------
__device__ __align__(16) __nv_bfloat16 g_A[(TT + 1) * BB * KP]; // 87.2 MB
__device__ __align__(16) __nv_bfloat16 g_W[NZP * KP];           // 0.86 MB
__device__ float    g_biasP[NZP];
__device__ double   g_bsum[CE_BLOCKS];
__device__ int      g_bcnt[CE_BLOCKS];
__device__ int      g_mask_is_byte;

// Per-row-group barriers, 256B padded (avoid L2 hash bit-7 pair-collide).
struct __align__(256) GroupBar { unsigned cnt; unsigned phase; unsigned pad[62]; };
__device__ GroupBar g_bars[8];       // cnt returns to 0; phase monotonic

// ----------------- scalar helpers -----------------
__device__ __forceinline__ float rcp_fast(float x) {
    float y;
    asm("rcp.approx.f32 %0, %1;" : "=f"(y) : "f"(x));
    return y;
}

// exp(x) with zero MUFU: FMA-only range reduction + 2^f poly + exponent add.
__device__ __forceinline__ float exp_fma(float x) {
    float x2 = x * 1.4426950408889634f;
    x2 = fminf(fmaxf(x2, -30.0f), 30.0f);
    float biased = x2 + 12582912.0f;            // 1.5 * 2^23
    int   ni = __float_as_int(biased) - 0x4B400000;
    float n = biased - 12582912.0f;
    float f = x2 - n;
    float p = 1.5403530e-4f;
    p = fmaf(p, f, 1.3333558e-3f);
    p = fmaf(p, f, 9.6181291e-3f);
    p = fmaf(p, f, 5.5504109e-2f);
    p = fmaf(p, f, 2.4022651e-1f);
    p = fmaf(p, f, 6.9314718e-1f);
    p = fmaf(p, f, 1.0f);
    return __int_as_float(__float_as_int(p) + (ni << 23));
}

// LSTM pointwise update (validated: FMA-exp + 2 RCP).
__device__ __forceinline__ void lstm_point(float iv, float jv, float fv, float ov,
                                           float c, float& cn, float& hn) {
    float ef = exp_fma(-(fv + 1.0f));
    float ei = exp_fma(-iv);
    float ej = exp_fma(2.0f * jv);
    float eo = exp_fma(-ov);
    float Af = 1.0f + ef;
    float Ai = 1.0f + ei;
    float Aj = ej + 1.0f;
    float Nj = ej - 1.0f;
    float AiAj = Ai * Aj;
    float num = fmaf(c, AiAj, Nj * Af);
    cn = num * rcp_fast(Af * AiAj);
    float ec = exp_fma(2.0f * cn);
    hn = (ec - 1.0f) * rcp_fast((1.0f + eo) * (ec + 1.0f));
}

// ----------------- async copy helpers -----------------
__device__ __forceinline__ void cp16(uint32_t dst_smem, const void* src) {
    asm volatile("cp.async.cg.shared.global [%0], [%1], 16;"
                 :: "r"(dst_smem), "l"(src));
}
__device__ __forceinline__ void cp_commit() {
    asm volatile("cp.async.commit_group;");
}
template <int N>
__device__ __forceinline__ void cp_wait() {
    asm volatile("cp.async.wait_group %0;" :: "n"(N));
}

// mma.sync m16n8k16 bf16 (sm_80+ PTX, legal on plain sm_100 target)
__device__ __forceinline__ void mma16816(float& d0, float& d1, float& d2, float& d3,
                                         uint32_t a0, uint32_t a1, uint32_t a2,
                                         uint32_t a3, uint32_t b0, uint32_t b1) {
    asm volatile(
        "mma.sync.aligned.m16n8k16.row.col.f32.bf16.bf16.f32 "
        "{%0,%1,%2,%3}, {%4,%5,%6,%7}, {%8,%9}, {%0,%1,%2,%3};"
        : "+f"(d0), "+f"(d1), "+f"(d2), "+f"(d3)
        : "r"(a0), "r"(a1), "r"(a2), "r"(a3), "r"(b0), "r"(b1));
}

__device__ __forceinline__ void ldsm4(uint32_t& r0, uint32_t& r1,
                                      uint32_t& r2, uint32_t& r3, uint32_t a) {
    asm volatile("ldmatrix.sync.aligned.m8n8.x4.shared.b16 {%0,%1,%2,%3}, [%4];"
                 : "=r"(r0), "=r"(r1), "=r"(r2), "=r"(r3) : "r"(a));
}
__device__ __forceinline__ void ldsm2(uint32_t& r0, uint32_t& r1, uint32_t a) {
    asm volatile("ldmatrix.sync.aligned.m8n8.x2.shared.b16 {%0,%1}, [%2];"
                 : "=r"(r0), "=r"(r1) : "r"(a));
}

// ----------------- setup kernels -----------------

__global__ void detect_k(const unsigned int* __restrict__ mw) {
    int idx = blockIdx.x * blockDim.x + threadIdx.x;
    if (idx < TOKENS / 4) {
        if (mw[idx] > 1u) g_mask_is_byte = 1;   // benign race, same value
    }
}

// Permuted bf16 weights g_W[c'][k], c' = 4p+g (orig col g*300+p); bias too.
__global__ void wbuild_k(const float* __restrict__ Wx,
                         const float* __restrict__ Wh,
                         const float* __restrict__ bias) {
    int idx = blockIdx.x * blockDim.x + threadIdx.x;
    if (idx < NZP * KP) {
        int cp = idx / KP, k = idx % KP;
        float v = 0.f;
        if (cp < NZ && k < KTOT) {
            int p = cp >> 2, g = cp & 3;
            v = (k < EE) ? Wx[k * NZ + g * HH + p] : Wh[(k - EE) * NZ + g * HH + p];
        }
        g_W[idx] = __float2bfloat16(v);
    }
    if (idx < NZP) {
        float v = 0.f;
        if (idx < NZ) v = bias[(idx & 3) * HH + (idx >> 2)];
        g_biasP[idx] = v;
    }
}

// Gather embeddings as bf16 pairs into A images; 2 threads per token.
__global__ void gather_k(const int* __restrict__ tokens,
                         const float* __restrict__ emb) {
    int idx = blockIdx.x * blockDim.x + threadIdx.x;
    if (idx >= 2 * TOKENS) return;
    int tok_i = idx >> 1;
    int half = idx & 1;
    int b = tok_i / TT, t = tok_i - b * TT;
    const float* er = emb + (size_t)tokens[tok_i] * EE;
    uint32_t* dst = reinterpret_cast<uint32_t*>(
        g_A + ((size_t)t * BB + b) * KP);
    int q0 = half * 13;
    int q1 = half ? 25 : 13;
    for (int q = q0; q < q1; ++q) {
        __nv_bfloat162 p2 = __floats2bfloat162_rn(er[2 * q], er[2 * q + 1]);
        dst[q] = *reinterpret_cast<uint32_t*>(&p2);
    }
}

// --------- persistent kernel: all 120 LSTM steps, 768 threads --------------
// 24 warps (6/SMSP). Warp w: m-tile w%8, n-group w/8 (3 n-tiles each).
// Progressive h stages (k-tiles 2/4/6/7) for fast first-stage availability;
// x-mma split around the group-barrier spin to cover both arrive skew and
// h-group-0 load latency.
__global__ __launch_bounds__(NTHR) void lstm_persist_k() {
    extern __shared__ __align__(16) char dyn[];
    __shared__ float bias_s[GN];
    __shared__ unsigned base_phase_s;

    char* const As = dyn;                       // [128][720B]
    char* const Ws = dyn + AS_BYTES;            // [72][720B]
    const uint32_t sA = (uint32_t)__cvta_generic_to_shared(As);
    const uint32_t sW = (uint32_t)__cvta_generic_to_shared(Ws);

    const int tid = threadIdx.x;
    const int warp = tid >> 5;
    const int lane = tid & 31;
    const int g = lane >> 2;
    const int tig = lane & 3;
    const int mt = warp & 7;         // m-tile 0..7
    const int ng = warp >> 3;        // n-group 0..2
    const int rb = blockIdx.x;
    const int cbk = blockIdx.y;
    const int pblk = cbk * POSB;
    const int m0 = mt * 16;

    if (tid == 0) base_phase_s = *(volatile unsigned*)&g_bars[rb].phase;

    auto load_cols = [&](const char* gbase, int c0, int c1) {
        const int span = c1 - c0;
        for (int i = tid; i < GM * span; i += NTHR) {
            int r = i / span, c = c0 + i - (i / span) * span;
            cp16(sA + r * AS_STRIDE + c * 16, gbase + r * (KP * 2) + c * 16);
        }
    };
    // h-col load in 4 progressive groups: chunks [6,10),[10,18),[18,30),[30,44)
    auto load_h_groups = [&](const char* gbase) {
        load_cols(gbase, 6, 10);  cp_commit();
        load_cols(gbase, 10, 18); cp_commit();
        load_cols(gbase, 18, 30); cp_commit();
        load_cols(gbase, 30, 44); cp_commit();
    };

    // initial loads: group0 = W + bias + A x-cols; then 4 h groups
    {
        const char* gWb = reinterpret_cast<const char*>(g_W + (size_t)cbk * GN * KP);
        for (int i = tid; i < WCH; i += NTHR) {
            int r = i / 44, c = i - (i / 44) * 44;
            cp16(sW + r * AS_STRIDE + c * 16, gWb + r * (KP * 2) + c * 16);
        }
        const char* gAb = reinterpret_cast<const char*>(g_A + ((size_t)rb * GM) * KP);
        load_cols(gAb, 0, 6);  cp_commit();
        load_h_groups(gAb);
        if (tid < GN) bias_s[tid] = g_biasP[cbk * GN + tid];
    }
    __syncthreads();
    const unsigned base_phase = base_phase_s;

    // ldmatrix lane addresses (fixed across steps; +kk*32 per k-tile)
    const int quad = lane >> 3, lr = lane & 7;
    const uint32_t aBase = sA + (uint32_t)(m0 + (quad & 1) * 8 + lr) * AS_STRIDE
                         + (uint32_t)(quad >> 1) * 16;
    // B pair base (n-tiles 3ng, 3ng+1) and single base (n-tile 3ng+2)
    const uint32_t bPair = sW + (uint32_t)((3 * ng + (lane >> 4)) * 8 + lr) * AS_STRIDE
                         + (uint32_t)((lane >> 3) & 1) * 16;
    uint32_t bSing;
    {
        int l2 = lane & 15;
        bSing = sW + (uint32_t)((3 * ng + 2) * 8 + (l2 & 7)) * AS_STRIDE
              + (uint32_t)(l2 >> 3) * 16;
    }
    const int rowlo = rb * GM + m0 + g;

    float creg[3];
#pragma unroll
    for (int u = 0; u < 3; ++u) creg[u] = 0.f;

    float acc[3][4];

    auto zero_acc = [&]() {
#pragma unroll
        for (int u = 0; u < 3; ++u)
#pragma unroll
            for (int e = 0; e < 4; ++e) acc[u][e] = 0.f;
    };
    auto mma_tiles = [&](int kk0, int kk1) {
        for (int kk = kk0; kk < kk1; ++kk) {
            const uint32_t ko = (uint32_t)kk * 32;
            uint32_t a0, a1, a2, a3;
            ldsm4(a0, a1, a2, a3, aBase + ko);
            uint32_t b0, b1, b2, b3;
            ldsm4(b0, b1, b2, b3, bPair + ko);
            mma16816(acc[0][0], acc[0][1], acc[0][2], acc[0][3],
                     a0, a1, a2, a3, b0, b1);
            mma16816(acc[1][0], acc[1][1], acc[1][2], acc[1][3],
                     a0, a1, a2, a3, b2, b3);
            uint32_t c0, c1;
            ldsm2(c0, c1, bSing + ko);
            mma16816(acc[2][0], acc[2][1], acc[2][2], acc[2][3],
                     a0, a1, a2, a3, c0, c1);
        }
    };

    // prologue: x k-tiles of t=0 (group0 = oldest of 5 pending -> wait<4>)
    zero_acc();
    cp_wait<4>();
    __syncthreads();
    mma_tiles(0, 3);

    for (int t = 0; t < TT; ++t) {
        // progressive h stages
        cp_wait<3>(); __syncthreads(); mma_tiles(3, 5);    // chunks [6,10)
        cp_wait<2>(); __syncthreads(); mma_tiles(5, 9);    // [10,18)
        cp_wait<1>(); __syncthreads(); mma_tiles(9, 15);   // [18,30)
        cp_wait<0>(); __syncthreads(); mma_tiles(15, 22);  // [30,44)
        __syncthreads();   // all warps done with As before x-prefetch

        const bool more = (t + 1 < TT);
        const char* gAn_b = reinterpret_cast<const char*>(
            g_A + ((size_t)(t + 1) * BB + rb * GM) * KP);
        if (more) {
            load_cols(gAn_b, 0, 6);    // x cols of t+1 (independent of h)
            cp_commit();
        }

        // ---- epilogue: regroup gates via shfl, LSTM update, h -> A[t+1] ----
        __nv_bfloat16* gAn = g_A + ((size_t)(t + 1) * BB) * KP;
#pragma unroll
        for (int u = 0; u < 3; ++u) {
            const int j = 3 * ng + u;
            float d0 = acc[u][0], d1 = acc[u][1], d2 = acc[u][2], d3 = acc[u][3];
            float x0 = __shfl_xor_sync(0xffffffffu, d0, 1);
            float x1 = __shfl_xor_sync(0xffffffffu, d1, 1);
            float x2 = __shfl_xor_sync(0xffffffffu, d2, 1);
            float x3 = __shfl_xor_sync(0xffffffffu, d3, 1);
            const bool odd = (tig & 1);
            float iv = odd ? x2 : d0;
            float jv = odd ? x3 : d1;
            float fv = odd ? d2 : x0;
            float ov = odd ? d3 : x1;
            int pl = 2 * j + (tig >> 1);
            int p = pblk + pl;
            int b = rowlo + (odd ? 8 : 0);
            iv += bias_s[4 * pl + 0];
            jv += bias_s[4 * pl + 1];
            fv += bias_s[4 * pl + 2];
            ov += bias_s[4 * pl + 3];
            float hn = 0.f;
            if (p < HH) {
                float cn;
                lstm_point(iv, jv, fv, ov, creg[u], cn, hn);
                creg[u] = cn;
            }
            float hp = __shfl_xor_sync(0xffffffffu, hn, 2);
            if (!(tig & 2) && p < HH) {
                __nv_bfloat162 hb = __floats2bfloat162_rn(hn, hp);
                *reinterpret_cast<uint32_t*>(&gAn[(size_t)b * KP + EE + p])
                    = *reinterpret_cast<uint32_t*>(&hb);
            }
        }

        if (more) {
            // ---- arrive (non-blocking) on this row-group's barrier ----
            __threadfence();
            __syncthreads();
            if (tid == 0) {
                if (atomicAdd(&g_bars[rb].cnt, 1u) == NGRP - 1) {
                    atomicExch(&g_bars[rb].cnt, 0u);
                    __threadfence();
                    atomicAdd(&g_bars[rb].phase, 1u);
                }
            }

            // ---- cover arrive/skew: x k-tiles 0-1 of t+1 ----
            zero_acc();
            cp_wait<0>();          // x prefetch resident
            __syncthreads();
            mma_tiles(0, 2);

            // ---- wait for group peers' h(t+1) ----
            if (tid == 0) {
                unsigned tgt = (unsigned)(t + 1);
                while ((*(volatile unsigned*)&g_bars[rb].phase) - base_phase < tgt) {}
            }
            __syncthreads();

            // ---- issue h loads, then cover group-0 latency with x tile 2 ----
            load_h_groups(gAn_b);
            mma_tiles(2, 3);
        }
    }
}

// ----------------- CE: projection + log-softmax + masked sum ----------------
// h for step t read as bf16 from A image t+1 (k = 50..349), contiguous/token.
__global__ void ce_k(const float* __restrict__ U, const float* __restrict__ b2,
                     const int* __restrict__ labels,
                     const void* __restrict__ maskp)
{
    __shared__ float Us[HH * CC];
    __shared__ float b2s[CC];
    __shared__ double sd[CE_TB];
    __shared__ int    sc[CE_TB];

    const int tid = threadIdx.x;
    const int t = blockIdx.x >> 3;
    const int b = ((blockIdx.x & 7) << 7) + tid;

    for (int i = tid; i < HH * CC; i += CE_TB) Us[i] = U[i];
    if (tid < CC) b2s[tid] = b2[tid];
    __syncthreads();

    float s0 = b2s[0], s1 = b2s[1], s2 = b2s[2], s3 = b2s[3], s4 = b2s[4];
    const uint32_t* hp = reinterpret_cast<const uint32_t*>(
        g_A + ((size_t)(t + 1) * BB + b) * KP + EE);
#pragma unroll 2
    for (int q = 0; q < HH / 2; ++q) {
        __nv_bfloat162 h2 = *reinterpret_cast<const __nv_bfloat162*>(&hp[q]);
        float h0 = __bfloat162float(h2.x);
        float h1 = __bfloat162float(h2.y);
        const float* u0 = &Us[(2 * q) * CC];
        const float* u1 = &Us[(2 * q + 1) * CC];
        s0 += h0 * u0[0] + h1 * u1[0];
        s1 += h0 * u0[1] + h1 * u1[1];
        s2 += h0 * u0[2] + h1 * u1[2];
        s3 += h0 * u0[3] + h1 * u1[3];
        s4 += h0 * u0[4] + h1 * u1[4];
    }

    float m = fmaxf(fmaxf(fmaxf(s0, s1), fmaxf(s2, s3)), s4);
    float sum = __expf(s0 - m) + __expf(s1 - m) + __expf(s2 - m)
              + __expf(s3 - m) + __expf(s4 - m);
    float lse = m + __logf(sum);
    int lab = labels[b * TT + t];
    float lc = (lab == 0) ? s0 : (lab == 1) ? s1 : (lab == 2) ? s2
             : (lab == 3) ? s3 : s4;
    float ce = lse - lc;
    int mk;
    if (g_mask_is_byte) mk = (((const unsigned char*)maskp)[b * TT + t] != 0);
    else                mk = (((const int*)maskp)[b * TT + t] != 0);

    sd[tid] = mk ? (double)ce : 0.0;
    sc[tid] = mk;
    __syncthreads();
    for (int off = CE_TB / 2; off; off >>= 1) {
        if (tid < off) { sd[tid] += sd[tid + off]; sc[tid] += sc[tid + off]; }
        __syncthreads();
    }
    if (tid == 0) { g_bsum[blockIdx.x] = sd[0]; g_bcnt[blockIdx.x] = sc[0]; }
}

__global__ void fin_k(float* out) {
    __shared__ double sd[256];
    __shared__ int    sc[256];
    int i = threadIdx.x;
    double s = 0.0; int c = 0;
    for (int j = i; j < CE_BLOCKS; j += 256) { s += g_bsum[j]; c += g_bcnt[j]; }
    sd[i] = s; sc[i] = c;
    __syncthreads();
    for (int off = 128; off; off >>= 1) {
        if (i < off) { sd[i] += sd[i + off]; sc[i] += sc[i + off]; }
        __syncthreads();
    }
    if (i == 0) out[0] = (float)(sd[0] / (double)sc[0]);
}

// ----------------- launcher -----------------
extern "C" void kernel_launch(void* const* d_in, const int* in_sizes, int n_in,
                              void* d_out, int out_size)
{
    const int*   tokens = (const int*)d_in[0];
    const int*   labels = (const int*)d_in[1];
    const void*  mask   = d_in[2];
    const float* emb    = (const float*)d_in[3];
    const float* Wx     = (const float*)d_in[4];
    const float* Wh     = (const float*)d_in[5];
    const float* bias   = (const float*)d_in[6];
    const float* U      = (const float*)d_in[7];
    const float* b2     = (const float*)d_in[8];
    float* out = (float*)d_out;

    static int smem_set = 0;
    if (!smem_set) {
        cudaFuncSetAttribute(lstm_persist_k,
                             cudaFuncAttributeMaxDynamicSharedMemorySize,
                             DYN_BYTES);
        smem_set = 1;
    }

    detect_k<<<(TOKENS / 4 + 255) / 256, 256>>>((const unsigned int*)mask);
    wbuild_k<<<(NZP * KP + 255) / 256, 256>>>(Wx, Wh, bias);
    gather_k<<<(2 * TOKENS + 255) / 256, 256>>>(tokens, emb);

    dim3 ggrid(BB / GM, NZP / GN);                 // (8, 17) = 136 blocks
    lstm_persist_k<<<ggrid, NTHR, DYN_BYTES>>>();  // launch #3 (profiled)

    ce_k<<<CE_BLOCKS, CE_TB>>>(U, b2, labels, mask);
    fin_k<<<1, 256>>>(out);
    (void)in_sizes; (void)n_in; (void)out_size;
}